// round 2
// baseline (speedup 1.0000x reference)
#include <cuda_runtime.h>
#include <cstdint>

// ============================================================================
// Problem constants
// ============================================================================
#define NFEAT 4096
#define MROWS 1024
#define KTOP  41.0f

// Scratch (device globals — allocation-free rule)
__device__ float g_alpha_topk[NFEAT];
__device__ float g_W[(size_t)NFEAT * NFEAT];

// RNA round fp32 -> tf32 (zero-mean; raw truncation would bias -2^-10)
__device__ __forceinline__ float tf32_round(float x) {
    uint32_t b = __float_as_uint(x);
    b = (b + 0x1000u) & 0xFFFFE000u;
    return __uint_as_float(b);
}

// ============================================================================
// Kernel 1: soft-top-k (Dykstra reduced to scalar-shift recurrence).
//   p_new in the reference is a constant vector => track z = y0 + S:
//   lam = (sum(clip(y0+S)) + n*p - k)/n;  S += p - lam;  p = lam.
//   Valid because y0 = alpha/0.01 in [0, 0.025] subset [0,1] (first-iter sum
//   in the reference uses unclipped y0, equal to clip(y0) here).
// ============================================================================
__global__ void alpha_topk_kernel(const float* __restrict__ alpha) {
    const int tid = threadIdx.x;  // 128 threads, 32 elems each
    float y0[32];
#pragma unroll
    for (int j = 0; j < 32; j++) y0[j] = alpha[tid + j * 128] / 0.01f;

    __shared__ float wsum[4];
    __shared__ float lam_sh;
    float S = 0.f, p = 0.f;

    for (int it = 0; it < 50; it++) {
        float local = 0.f;
#pragma unroll
        for (int j = 0; j < 32; j++) {
            float v = y0[j] + S;
            v = fminf(fmaxf(v, 0.f), 1.f);
            local += v;
        }
#pragma unroll
        for (int o = 16; o > 0; o >>= 1) local += __shfl_xor_sync(0xffffffffu, local, o);
        if ((tid & 31) == 0) wsum[tid >> 5] = local;
        __syncthreads();
        if (tid == 0) {
            float s4 = wsum[0] + wsum[1] + wsum[2] + wsum[3];
            lam_sh = (s4 + (float)NFEAT * p - KTOP) / (float)NFEAT;
        }
        __syncthreads();
        float lam = lam_sh;
        S += p - lam;
        p = lam;
    }
#pragma unroll
    for (int j = 0; j < 32; j++) {
        float v = y0[j] + S;
        g_alpha_topk[tid + j * 128] = fminf(fmaxf(v, 0.f), 1.f);
    }
}

// ============================================================================
// Kernel 2: materialize W[r,c] = a[i]*V[i,c], r=(i+c)%n — smem diagonal
// transpose: coalesced V reads AND coalesced W writes. W stored tf32-rounded.
// ============================================================================
#define TI 64
#define TC 128
#define TSTR 132   // mult of 4 (aligned float4 STS); diag read stride -131 -> conflict-free

__global__ __launch_bounds__(256) void build_w_kernel(const float* __restrict__ V) {
    __shared__ float tile[TI * TSTR];
    const int tid = threadIdx.x;
    const int i0 = blockIdx.y * TI;
    const int c0 = blockIdx.x * TC;

#pragma unroll
    for (int pp = 0; pp < 8; pp++) {
        int idx = tid + pp * 256;        // 0..2047
        int il  = idx >> 5;              // 0..63
        int jq  = idx & 31;              // float4 index 0..31
        float a = g_alpha_topk[i0 + il];
        float4 v = *reinterpret_cast<const float4*>(V + (size_t)(i0 + il) * NFEAT + c0 + jq * 4);
        float4 w;
        w.x = tf32_round(a * v.x);
        w.y = tf32_round(a * v.y);
        w.z = tf32_round(a * v.z);
        w.w = tf32_round(a * v.w);
        *reinterpret_cast<float4*>(&tile[il * TSTR + jq * 4]) = w;
    }
    __syncthreads();

    const int sub = tid >> 6;   // 0..3
    const int l64 = tid & 63;
    for (int base = 0; base < TI + TC - 1; base += 4) {
        int d = base + sub;
        if (d < TI + TC - 1) {
            int ccLo = max(0, d - (TI - 1));
            int ccHi = min(TC - 1, d);
            int cc = ccLo + l64;
            if (cc <= ccHi) {
                int il = d - cc;
                int r = (i0 + c0 + d) & (NFEAT - 1);
                g_W[(size_t)r * NFEAT + c0 + cc] = tile[il * TSTR + cc];
            }
        }
    }
}

// ============================================================================
// Kernel 3: GEMM  out[1024,4096] = X @ W^T.  BM=128, BN=128, BK=32,
// double-buffered smem. Two device-side implementations selected by the
// actual compile target:
//   - sm_103a pass (__CUDA_ARCH_FEAT_SM103_ALL): tcgen05 kind::tf32 SS MMA
//   - base sm_103 pass: mma.sync.aligned.m16n8k8 tf32 (Ampere-era tensor path)
// Identical launch config for both: grid(32,8), 256 threads, 72 KB dyn smem.
// ============================================================================
#define TMB 128
#define TNB 128
#define GEMM_SMEM 73728
#define NSTAGES (NFEAT / 32)              // 128

#if defined(__CUDA_ARCH_FEAT_SM103_ALL)
// ---------------- tcgen05 helpers (only in the 103a pass) ----------------
__device__ __forceinline__ uint32_t smem_to_u32(const void* p) {
    uint32_t a;
    asm("{ .reg .u64 t; cvta.to.shared.u64 t, %1; cvt.u32.u64 %0, t; }" : "=r"(a) : "l"(p));
    return a;
}
__device__ __forceinline__ uint32_t elect_one_pred() {
    uint32_t pred;
    asm volatile("{\n\t.reg .pred p;\n\telect.sync _|p, 0xFFFFFFFF;\n\tselp.b32 %0, 1, 0, p;\n\t}"
                 : "=r"(pred));
    return pred;
}
#define MBARRIER_INIT(addr, cnt) \
    asm volatile("mbarrier.init.shared.b64 [%0], %1;" :: "r"((uint32_t)(addr)), "r"((uint32_t)(cnt)) : "memory")
#define MBARRIER_WAIT_PARITY(mbar_smem_addr, phase_parity) do { \
    uint32_t _mbar = (uint32_t)(mbar_smem_addr); \
    uint32_t _parity = (uint32_t)(phase_parity); \
    uint32_t _done; \
    asm volatile( \
        "{\n\t.reg .pred p;\n\t" \
        "mbarrier.try_wait.parity.acquire.cta.shared::cta.b64 p, [%1], %2;\n\t" \
        "selp.b32 %0, 1, 0, p;\n\t}" \
        : "=r"(_done) : "r"(_mbar), "r"(_parity) : "memory"); \
    if (!_done) { \
        asm volatile( \
            "{\n\t.reg .pred P1;\n\t" \
            "WAIT_LOOP_%=:\n\t" \
            "mbarrier.try_wait.parity.acquire.cta.shared::cta.b64 P1, [%0], %1, 0x989680;\n\t" \
            "@P1 bra.uni WAIT_DONE_%=;\n\t" \
            "bra.uni WAIT_LOOP_%=;\n\t" \
            "WAIT_DONE_%=:\n\t}" \
            :: "r"(_mbar), "r"(_parity) : "memory"); \
    } \
} while(0)
#define TCGEN05_ALLOC(smem_result_addr, nCols) \
    asm volatile("tcgen05.alloc.cta_group::1.sync.aligned.shared::cta.b32 [%0], %1;" \
                 :: "r"((uint32_t)(smem_result_addr)), "r"((uint32_t)(nCols)) : "memory")
#define TCGEN05_DEALLOC(tmem_addr, nCols) \
    asm volatile("tcgen05.dealloc.cta_group::1.sync.aligned.b32 %0, %1;" \
                 :: "r"(tmem_addr), "r"((uint32_t)(nCols)))
#define TCGEN05_RELINQUISH_ALLOC_PERMIT() \
    asm volatile("tcgen05.relinquish_alloc_permit.cta_group::1.sync.aligned;")
#define TCGEN05_COMMIT(mbar_smem_addr) \
    asm volatile("tcgen05.commit.cta_group::1.mbarrier::arrive::one.shared::cluster.b64 [%0];" \
                 :: "r"((uint32_t)(mbar_smem_addr)) : "memory")
#define TCGEN05_FENCE_AFTER()  asm volatile("tcgen05.fence::after_thread_sync;" ::: "memory")
#define TCGEN05_FENCE_BEFORE() asm volatile("tcgen05.fence::before_thread_sync;" ::: "memory")
#define TCGEN05_WAIT_LD()      asm volatile("tcgen05.wait::ld.sync.aligned;" ::: "memory")
#define TCGEN05_LD_32X32B_X32(r, tmem_addr) \
    asm volatile( \
        "tcgen05.ld.sync.aligned.32x32b.x32.b32 " \
        "{%0, %1, %2, %3, %4, %5, %6, %7, " \
        " %8, %9, %10, %11, %12, %13, %14, %15, " \
        " %16, %17, %18, %19, %20, %21, %22, %23, " \
        " %24, %25, %26, %27, %28, %29, %30, %31}, [%32];" \
        : "=r"((r)[0]),  "=r"((r)[1]),  "=r"((r)[2]),  "=r"((r)[3]), \
          "=r"((r)[4]),  "=r"((r)[5]),  "=r"((r)[6]),  "=r"((r)[7]), \
          "=r"((r)[8]),  "=r"((r)[9]),  "=r"((r)[10]), "=r"((r)[11]), \
          "=r"((r)[12]), "=r"((r)[13]), "=r"((r)[14]), "=r"((r)[15]), \
          "=r"((r)[16]), "=r"((r)[17]), "=r"((r)[18]), "=r"((r)[19]), \
          "=r"((r)[20]), "=r"((r)[21]), "=r"((r)[22]), "=r"((r)[23]), \
          "=r"((r)[24]), "=r"((r)[25]), "=r"((r)[26]), "=r"((r)[27]), \
          "=r"((r)[28]), "=r"((r)[29]), "=r"((r)[30]), "=r"((r)[31]) \
        : "r"(tmem_addr))
#define SMEM_SWIZZLE_128B(b) ((b) ^ (((b) >> 3) & 0x70))
static constexpr uint64_t SMEM_DESC_BASE_SW128 =
    (uint64_t(2) << 61) | (uint64_t(1) << 46) | (uint64_t(64) << 32) | (uint64_t(1) << 16);
#define MAKE_SMEM_DESC(base_addr) \
    (SMEM_DESC_BASE_SW128 | ((uint64_t)((base_addr) >> 4) & 0x3FFF))

__device__ __forceinline__ void mma_tf32_ss(uint32_t d_tmem, uint64_t a_desc, uint64_t b_desc,
                                            uint32_t idesc, bool acc) {
    uint32_t en = acc ? 1u : 0u;
    asm volatile(
        "{\n\t.reg .pred p;\n\tsetp.ne.u32 p, %5, 0;\n\t"
        "tcgen05.mma.cta_group::1.kind::tf32 [%0], %1, %2, %3, {%4, %4, %4, %4}, p;\n\t}"
        :: "r"(d_tmem), "l"(a_desc), "l"(b_desc), "r"(idesc), "r"(0u), "r"(en)
        : "memory");
}

// idesc: dtype F32 (1<<4), atype TF32 (2<<7), btype TF32 (2<<10), N/8<<17, M/16<<24
static constexpr uint32_t GEMM_IDESC =
    (1u << 4) | (2u << 7) | (2u << 10) | ((TNB / 8) << 17) | ((TMB / 16) << 24);
#define A_BYTES (TMB * 128)
#define B_BYTES (TNB * 128)
#define OFF_TMEMPTR 0
#define OFF_MBAR 8
#define OFF_A 1024
#define OFF_B (OFF_A + 2 * A_BYTES)
#endif  // __CUDA_ARCH_FEAT_SM103_ALL

// ---------------- fallback mma.sync helper (valid on sm_80+) ----------------
__device__ __forceinline__ void mma16n8k8(float* c, const uint32_t* a, const uint32_t* b) {
    asm volatile(
        "mma.sync.aligned.m16n8k8.row.col.f32.tf32.tf32.f32 "
        "{%0,%1,%2,%3}, {%4,%5,%6,%7}, {%8,%9}, {%0,%1,%2,%3};"
        : "+f"(c[0]), "+f"(c[1]), "+f"(c[2]), "+f"(c[3])
        : "r"(a[0]), "r"(a[1]), "r"(a[2]), "r"(a[3]), "r"(b[0]), "r"(b[1]));
}

#define FB_STR 36   // padded row stride (floats): float4-aligned + conflict-free frags
#define FB_BUF (128 * FB_STR)

__global__ __launch_bounds__(256, 1)
void gemm_kernel(const float* __restrict__ X, float* __restrict__ OUT) {
    extern __shared__ char smem[];
    const int tid  = threadIdx.x;
    const int wid  = tid >> 5;
    const int lane = tid & 31;
    const int m0 = blockIdx.y * TMB;
    const int n0 = blockIdx.x * TNB;

#if defined(__CUDA_ARCH_FEAT_SM103_ALL)
    // ======================= tcgen05 path =======================
    const uint32_t sb = smem_to_u32(smem);
    if (wid == 0) {
        TCGEN05_ALLOC(sb + OFF_TMEMPTR, TNB);
        TCGEN05_RELINQUISH_ALLOC_PERMIT();
    }
    if (tid == 0) {
        MBARRIER_INIT(sb + OFF_MBAR, 1);
        MBARRIER_INIT(sb + OFF_MBAR + 8, 1);
    }
    __syncthreads();
    uint32_t tmem;
    asm volatile("ld.shared.b32 %0, [%1];" : "=r"(tmem) : "r"(sb + OFF_TMEMPTR));

    for (int s = 0; s < NSTAGES; s++) {
        const int buf = s & 1;
        const uint32_t mbar = sb + OFF_MBAR + buf * 8;
        if (s >= 2) {
            int u = (s >> 1) - 1;
            MBARRIER_WAIT_PARITY(mbar, u & 1);
        }
        const int k0 = s * 32;
        const uint32_t abase = OFF_A + buf * A_BYTES;
        const uint32_t bbase = OFF_B + buf * B_BYTES;

#pragma unroll
        for (int pp = 0; pp < 4; pp++) {
            int idx = tid + pp * 256;
            int m = idx >> 3, j = idx & 7;
            float4 v = *reinterpret_cast<const float4*>(
                X + (size_t)(m0 + m) * NFEAT + k0 + j * 4);
            v.x = tf32_round(v.x); v.y = tf32_round(v.y);
            v.z = tf32_round(v.z); v.w = tf32_round(v.w);
            uint32_t off = SMEM_SWIZZLE_128B((uint32_t)(m * 128 + j * 16));
            *reinterpret_cast<float4*>(smem + abase + off) = v;
        }
#pragma unroll
        for (int pp = 0; pp < 4; pp++) {
            int idx = tid + pp * 256;
            int nn = idx >> 3, j = idx & 7;
            float4 v = *reinterpret_cast<const float4*>(
                g_W + (size_t)(n0 + nn) * NFEAT + k0 + j * 4);
            uint32_t off = SMEM_SWIZZLE_128B((uint32_t)(nn * 128 + j * 16));
            *reinterpret_cast<float4*>(smem + bbase + off) = v;
        }
        asm volatile("fence.proxy.async.shared::cta;" ::: "memory");
        __syncthreads();

        if (wid == 0) {
            if (elect_one_pred()) {
                uint64_t ad = MAKE_SMEM_DESC(sb + abase);
                uint64_t bd = MAKE_SMEM_DESC(sb + bbase);
#pragma unroll
                for (int ks = 0; ks < 4; ks++)   // 4 x K=8 tf32 steps = K=32
                    mma_tf32_ss(tmem, ad + ks * 2, bd + ks * 2, GEMM_IDESC,
                                (s > 0) || (ks > 0));
                TCGEN05_COMMIT(mbar);
            }
        }
    }

    MBARRIER_WAIT_PARITY(sb + OFF_MBAR, 1);       // last use parity: 63&1 = 1
    MBARRIER_WAIT_PARITY(sb + OFF_MBAR + 8, 1);
    TCGEN05_FENCE_AFTER();

    if (wid < 4) {
        float* orow = OUT + (size_t)(m0 + wid * 32 + lane) * NFEAT + n0;
        for (int cb = 0; cb < TNB; cb += 32) {
            uint32_t r[32];
            TCGEN05_LD_32X32B_X32(r, tmem + cb);
            TCGEN05_WAIT_LD();
#pragma unroll
            for (int q = 0; q < 8; q++) {
                float4 v;
                v.x = __uint_as_float(r[q * 4 + 0]);
                v.y = __uint_as_float(r[q * 4 + 1]);
                v.z = __uint_as_float(r[q * 4 + 2]);
                v.w = __uint_as_float(r[q * 4 + 3]);
                *reinterpret_cast<float4*>(orow + cb + q * 4) = v;
            }
        }
        TCGEN05_FENCE_BEFORE();
    }
    __syncthreads();
    if (wid == 0) TCGEN05_DEALLOC(tmem, TNB);

#else
    // ======================= mma.sync fallback =======================
    float* sA = reinterpret_cast<float*>(smem);              // [2][128*36]
    float* sB = reinterpret_cast<float*>(smem) + 2 * FB_BUF; // [2][128*36]
    const int wm = wid >> 2;   // 0..1
    const int wn = wid & 3;    // 0..3

    float acc[16][4];
#pragma unroll
    for (int i = 0; i < 16; i++)
        acc[i][0] = acc[i][1] = acc[i][2] = acc[i][3] = 0.f;

    float4 rA[4], rB[4];
    auto ldg_stage = [&](int s) {
        const int k0 = s * 32;
#pragma unroll
        for (int p = 0; p < 4; p++) {
            int idx = tid + p * 256;
            int row = idx >> 3, j = idx & 7;
            float4 v = *reinterpret_cast<const float4*>(
                X + (size_t)(m0 + row) * NFEAT + k0 + j * 4);
            v.x = tf32_round(v.x); v.y = tf32_round(v.y);
            v.z = tf32_round(v.z); v.w = tf32_round(v.w);
            rA[p] = v;
            rB[p] = *reinterpret_cast<const float4*>(
                g_W + (size_t)(n0 + row) * NFEAT + k0 + j * 4);
        }
    };
    auto sts_stage = [&](int buf) {
#pragma unroll
        for (int p = 0; p < 4; p++) {
            int idx = tid + p * 256;
            int row = idx >> 3, j = idx & 7;
            *reinterpret_cast<float4*>(&sA[buf * FB_BUF + row * FB_STR + j * 4]) = rA[p];
            *reinterpret_cast<float4*>(&sB[buf * FB_BUF + row * FB_STR + j * 4]) = rB[p];
        }
    };

    ldg_stage(0);
    sts_stage(0);
    __syncthreads();

    for (int s = 0; s < NSTAGES; s++) {
        const int buf = s & 1;
        if (s + 1 < NSTAGES) ldg_stage(s + 1);

        const float* tA = sA + buf * FB_BUF + wm * 64 * FB_STR;
        const float* tB = sB + buf * FB_BUF + wn * 32 * FB_STR;
#pragma unroll
        for (int ks = 0; ks < 4; ks++) {
            const int kk = ks * 8;
            uint32_t afr[4][4], bfr[4][2];
#pragma unroll
            for (int mi = 0; mi < 4; mi++) {
                int r = mi * 16 + (lane >> 2);
                int cA = kk + (lane & 3);
                afr[mi][0] = __float_as_uint(tA[r * FB_STR + cA]);
                afr[mi][1] = __float_as_uint(tA[(r + 8) * FB_STR + cA]);
                afr[mi][2] = __float_as_uint(tA[r * FB_STR + cA + 4]);
                afr[mi][3] = __float_as_uint(tA[(r + 8) * FB_STR + cA + 4]);
            }
#pragma unroll
            for (int ni = 0; ni < 4; ni++) {
                int nn = ni * 8 + (lane >> 2);
                int cB = kk + (lane & 3);
                bfr[ni][0] = __float_as_uint(tB[nn * FB_STR + cB]);
                bfr[ni][1] = __float_as_uint(tB[nn * FB_STR + cB + 4]);
            }
#pragma unroll
            for (int mi = 0; mi < 4; mi++)
#pragma unroll
                for (int ni = 0; ni < 4; ni++)
                    mma16n8k8(acc[mi * 4 + ni], afr[mi], bfr[ni]);
        }

        if (s + 1 < NSTAGES) sts_stage(buf ^ 1);
        __syncthreads();
    }

    // Epilogue: c0,c1 at (row, col..col+1); c2,c3 at (row+8, col..col+1)
#pragma unroll
    for (int mi = 0; mi < 4; mi++) {
        int r = m0 + wm * 64 + mi * 16 + (lane >> 2);
#pragma unroll
        for (int ni = 0; ni < 4; ni++) {
            int c = n0 + wn * 32 + ni * 8 + (lane & 3) * 2;
            float2 v0 = make_float2(acc[mi * 4 + ni][0], acc[mi * 4 + ni][1]);
            float2 v1 = make_float2(acc[mi * 4 + ni][2], acc[mi * 4 + ni][3]);
            *reinterpret_cast<float2*>(OUT + (size_t)r * NFEAT + c) = v0;
            *reinterpret_cast<float2*>(OUT + (size_t)(r + 8) * NFEAT + c) = v1;
        }
    }
#endif
}

// ============================================================================
// Launch
// ============================================================================
extern "C" void kernel_launch(void* const* d_in, const int* in_sizes, int n_in,
                              void* d_out, int out_size) {
    const float* x = nullptr;
    const float* V = nullptr;
    const float* alpha = nullptr;
    for (int i = 0; i < n_in; i++) {
        if (in_sizes[i] == NFEAT)               alpha = (const float*)d_in[i];
        else if (in_sizes[i] == MROWS * NFEAT)  x     = (const float*)d_in[i];
        else                                    V     = (const float*)d_in[i];
    }
    float* out = (float*)d_out;

    cudaFuncSetAttribute(gemm_kernel, cudaFuncAttributeMaxDynamicSharedMemorySize, GEMM_SMEM);

    alpha_topk_kernel<<<1, 128>>>(alpha);
    build_w_kernel<<<dim3(NFEAT / TC, NFEAT / TI), 256>>>(V);
    gemm_kernel<<<dim3(NFEAT / TNB, MROWS / TMB), 256, GEMM_SMEM>>>(x, out);
}

// round 3
// speedup vs baseline: 1.2451x; 1.2451x over previous
#include <cuda_runtime.h>
#include <cuda_fp16.h>
#include <cstdint>

// ============================================================================
// Problem constants
// ============================================================================
#define NFEAT 4096
#define MROWS 1024
#define KTOP  41.0f
#define WSCALE 4096.0f          // 2^12, exact power of two
#define INV_WSCALE (1.0f/4096.0f)

// Scratch (device globals — allocation-free rule)
__device__ float g_alpha_topk[NFEAT];
__device__ __align__(128) __half g_Wh[(size_t)NFEAT * NFEAT];   // W * 2^12, fp16
__device__ __align__(128) __half g_Xh[(size_t)MROWS * NFEAT];   // x, fp16

// ============================================================================
// Small PTX helpers (base-arch safe: sm_80+ features only)
// ============================================================================
__device__ __forceinline__ uint32_t smem_to_u32(const void* p) {
    uint32_t a;
    asm("{ .reg .u64 t; cvta.to.shared.u64 t, %1; cvt.u32.u64 %0, t; }" : "=r"(a) : "l"(p));
    return a;
}
__device__ __forceinline__ void cp16(uint32_t dst_smem, const void* src) {
    asm volatile("cp.async.cg.shared.global [%0], [%1], 16;" :: "r"(dst_smem), "l"(src) : "memory");
}
#define CP_COMMIT() asm volatile("cp.async.commit_group;" ::: "memory")
#define CP_WAIT1()  asm volatile("cp.async.wait_group 1;"  ::: "memory")

__device__ __forceinline__ void mma16816(float* c, const uint32_t* a, const uint32_t* b) {
    asm volatile(
        "mma.sync.aligned.m16n8k16.row.col.f32.f16.f16.f32 "
        "{%0,%1,%2,%3}, {%4,%5,%6,%7}, {%8,%9}, {%0,%1,%2,%3};"
        : "+f"(c[0]), "+f"(c[1]), "+f"(c[2]), "+f"(c[3])
        : "r"(a[0]), "r"(a[1]), "r"(a[2]), "r"(a[3]), "r"(b[0]), "r"(b[1]));
}

// ============================================================================
// Kernel 1: soft-top-k (Dykstra collapsed to scalar-shift recurrence).
//   lam = (sum(clip(y0+S,0,1)) + n*p - k)/n;  S += p - lam;  p = lam.
//   Contraction factor (1 - n_active/n) ~ 0.1 => fixed point in ~15-20 iters;
//   early-break when |dS| < 1e-10 (uniform branch, deterministic).
// ============================================================================
__global__ void alpha_topk_kernel(const float* __restrict__ alpha) {
    const int tid  = threadIdx.x;        // 256 threads, 16 elems each
    const int wid  = tid >> 5;
    const int lane = tid & 31;
    float y0[16];
#pragma unroll
    for (int j = 0; j < 16; j++) y0[j] = alpha[tid + j * 256] * 100.0f;  // /0.01

    __shared__ float wsum[2][8];
    float S = 0.f, p = 0.f;

    for (int it = 0; it < 50; it++) {
        float local = 0.f;
#pragma unroll
        for (int j = 0; j < 16; j++) local += __saturatef(y0[j] + S);
#pragma unroll
        for (int o = 16; o > 0; o >>= 1) local += __shfl_xor_sync(0xffffffffu, local, o);
        if (lane == 0) wsum[it & 1][wid] = local;
        __syncthreads();
        float s8 = 0.f;
#pragma unroll
        for (int w = 0; w < 8; w++) s8 += wsum[it & 1][w];
        float lam = (s8 + (float)NFEAT * p - KTOP) / (float)NFEAT;
        float dS = p - lam;
        S += dS;
        p = lam;
        if (fabsf(dS) < 1e-10f) break;   // uniform across all threads
    }
#pragma unroll
    for (int j = 0; j < 16; j++)
        g_alpha_topk[tid + j * 256] = __saturatef(y0[j] + S);
}

// ============================================================================
// Kernel 2: x -> fp16 (one-time; x is reused 32x in the GEMM)
// ============================================================================
__global__ void xhalf_kernel(const float* __restrict__ X) {
    int i = (blockIdx.x * 256 + threadIdx.x) * 4;   // 4 floats per thread
    float4 v = *reinterpret_cast<const float4*>(X + i);
    __half2 h0 = __floats2half2_rn(v.x, v.y);
    __half2 h1 = __floats2half2_rn(v.z, v.w);
    uint2 packed;
    packed.x = *reinterpret_cast<uint32_t*>(&h0);
    packed.y = *reinterpret_cast<uint32_t*>(&h1);
    *reinterpret_cast<uint2*>(&g_Xh[i]) = packed;
}

// ============================================================================
// Kernel 3: materialize Wh[r,c] = 2^12 * a[i]*V[i,c], r=(i+c)%n — smem diagonal
// transpose: coalesced V reads AND coalesced Wh writes (fp16).
// ============================================================================
#define TI 64
#define TC 128
#define TSTR 132   // mult of 4 (aligned float4 STS); diag read conflict-free

__global__ __launch_bounds__(256) void build_w_kernel(const float* __restrict__ V) {
    __shared__ float tile[TI * TSTR];
    const int tid = threadIdx.x;
    const int i0 = blockIdx.y * TI;
    const int c0 = blockIdx.x * TC;

#pragma unroll
    for (int pp = 0; pp < 8; pp++) {
        int idx = tid + pp * 256;        // 0..2047
        int il  = idx >> 5;              // 0..63
        int jq  = idx & 31;              // float4 index 0..31
        float a = g_alpha_topk[i0 + il] * WSCALE;
        float4 v = *reinterpret_cast<const float4*>(V + (size_t)(i0 + il) * NFEAT + c0 + jq * 4);
        float4 w;
        w.x = a * v.x; w.y = a * v.y; w.z = a * v.z; w.w = a * v.w;
        *reinterpret_cast<float4*>(&tile[il * TSTR + jq * 4]) = w;
    }
    __syncthreads();

    const int sub = tid >> 6;   // 0..3
    const int l64 = tid & 63;
    for (int base = 0; base < TI + TC - 1; base += 4) {
        int d = base + sub;
        if (d < TI + TC - 1) {
            int ccLo = max(0, d - (TI - 1));
            int ccHi = min(TC - 1, d);
            int cc = ccLo + l64;
            if (cc <= ccHi) {
                int il = d - cc;
                int r = (i0 + c0 + d) & (NFEAT - 1);
                g_Wh[(size_t)r * NFEAT + c0 + cc] = __float2half_rn(tile[il * TSTR + cc]);
            }
        }
    }
}

// ============================================================================
// Kernel 4: fp16 GEMM  out[1024,4096] = (Xh @ Wh^T) * 2^-12, fp32 accumulate.
//   BM=128, BN=128, BK=64 halves (128B rows), 3-stage cp.async pipeline,
//   SW128-xor swizzle (no padding), one __syncthreads per stage, 256 threads,
//   2 CTAs/SM. Warp tile 64x32, m16n8k16, 64 mma/warp/stage.
// ============================================================================
#define BM 128
#define BN 128
#define NS (NFEAT / 64)          // 64 K-stages
#define STAGE_A 16384            // 128 rows x 128 B
#define STAGE_B 16384
#define STAGE_BYTES (STAGE_A + STAGE_B)
#define GEMM_SMEM (3 * STAGE_BYTES)      // 98304 B

__device__ __forceinline__ void issue_stage(int s, uint32_t sb, int m0, int n0, int tid) {
    if (s < NS) {
        const int buf = s % 3;
        const int k0h = s * 64;
#pragma unroll
        for (int p = 0; p < 4; p++) {
            int idx = tid + p * 256;     // 0..1023
            int row = idx >> 3, j = idx & 7;
            uint32_t off = (uint32_t)(row * 128 + j * 16);
            uint32_t sw  = off ^ (uint32_t)((row & 7) << 4);
            cp16(sb + buf * STAGE_BYTES + sw,
                 g_Xh + (size_t)(m0 + row) * NFEAT + k0h + j * 8);
        }
#pragma unroll
        for (int p = 0; p < 4; p++) {
            int idx = tid + p * 256;
            int row = idx >> 3, j = idx & 7;
            uint32_t off = (uint32_t)(row * 128 + j * 16);
            uint32_t sw  = off ^ (uint32_t)((row & 7) << 4);
            cp16(sb + buf * STAGE_BYTES + STAGE_A + sw,
                 g_Wh + (size_t)(n0 + row) * NFEAT + k0h + j * 8);
        }
    }
    CP_COMMIT();   // always commit (empty group past the end keeps wait counts right)
}

__global__ __launch_bounds__(256, 2)
void gemm_kernel(float* __restrict__ OUT) {
    extern __shared__ char smem[];
    const uint32_t sb = smem_to_u32(smem);
    const int tid  = threadIdx.x;
    const int wid  = tid >> 5;
    const int lane = tid & 31;
    const int t4   = lane >> 2;          // 0..7 (group)
    const int tq   = lane & 3;           // 0..3 (thread-in-group)
    const int wm   = wid >> 2;           // 0..1 -> 64-row slab
    const int wn   = wid & 3;            // 0..3 -> 32-col slab
    const int m0 = blockIdx.y * BM;
    const int n0 = blockIdx.x * BN;

    float acc[16][4];
#pragma unroll
    for (int i = 0; i < 16; i++)
        acc[i][0] = acc[i][1] = acc[i][2] = acc[i][3] = 0.f;

    // Per-thread constant base byte offsets (row*128 + tq*4); swizzle xor is
    // constant (t4<<4) because every accessed row == t4 (mod 8).
    uint32_t abase[4], bbase[4];
#pragma unroll
    for (int mi = 0; mi < 4; mi++)
        abase[mi] = (uint32_t)((wm * 64 + mi * 16 + t4) * 128 + tq * 4);
#pragma unroll
    for (int ni = 0; ni < 4; ni++)
        bbase[ni] = (uint32_t)((wn * 32 + ni * 8 + t4) * 128 + tq * 4);
    const uint32_t swz = (uint32_t)(t4 << 4);

    issue_stage(0, sb, m0, n0, tid);
    issue_stage(1, sb, m0, n0, tid);

    for (int s = 0; s < NS; s++) {
        CP_WAIT1();
        __syncthreads();
        const char* bufA = smem + (s % 3) * STAGE_BYTES;
        const char* bufB = bufA + STAGE_A;

#pragma unroll
        for (int ks = 0; ks < 4; ks++) {
            const uint32_t ko = (uint32_t)(ks * 32);
            uint32_t afr[4][4], bfr[4][2];
#pragma unroll
            for (int mi = 0; mi < 4; mi++) {
                uint32_t a0 = (abase[mi] + ko) ^ swz;
                uint32_t a2 = (abase[mi] + ko + 16) ^ swz;
                afr[mi][0] = *reinterpret_cast<const uint32_t*>(bufA + a0);
                afr[mi][1] = *reinterpret_cast<const uint32_t*>(bufA + a0 + 1024);
                afr[mi][2] = *reinterpret_cast<const uint32_t*>(bufA + a2);
                afr[mi][3] = *reinterpret_cast<const uint32_t*>(bufA + a2 + 1024);
            }
#pragma unroll
            for (int ni = 0; ni < 4; ni++) {
                uint32_t b0 = (bbase[ni] + ko) ^ swz;
                uint32_t b1 = (bbase[ni] + ko + 16) ^ swz;
                bfr[ni][0] = *reinterpret_cast<const uint32_t*>(bufB + b0);
                bfr[ni][1] = *reinterpret_cast<const uint32_t*>(bufB + b1);
            }
#pragma unroll
            for (int mi = 0; mi < 4; mi++)
#pragma unroll
                for (int ni = 0; ni < 4; ni++)
                    mma16816(acc[mi * 4 + ni], afr[mi], bfr[ni]);
        }

        issue_stage(s + 2, sb, m0, n0, tid);
    }

    // Epilogue: undo 2^12 W scaling; c0,c1 -> (r, col..col+1); c2,c3 -> r+8.
#pragma unroll
    for (int mi = 0; mi < 4; mi++) {
        int r = m0 + wm * 64 + mi * 16 + t4;
#pragma unroll
        for (int ni = 0; ni < 4; ni++) {
            int c = n0 + wn * 32 + ni * 8 + tq * 2;
            float* a = acc[mi * 4 + ni];
            float2 v0 = make_float2(a[0] * INV_WSCALE, a[1] * INV_WSCALE);
            float2 v1 = make_float2(a[2] * INV_WSCALE, a[3] * INV_WSCALE);
            *reinterpret_cast<float2*>(OUT + (size_t)r * NFEAT + c) = v0;
            *reinterpret_cast<float2*>(OUT + (size_t)(r + 8) * NFEAT + c) = v1;
        }
    }
}

// ============================================================================
// Launch
// ============================================================================
extern "C" void kernel_launch(void* const* d_in, const int* in_sizes, int n_in,
                              void* d_out, int out_size) {
    const float* x = nullptr;
    const float* V = nullptr;
    const float* alpha = nullptr;
    for (int i = 0; i < n_in; i++) {
        if (in_sizes[i] == NFEAT)               alpha = (const float*)d_in[i];
        else if (in_sizes[i] == MROWS * NFEAT)  x     = (const float*)d_in[i];
        else                                    V     = (const float*)d_in[i];
    }
    float* out = (float*)d_out;

    cudaFuncSetAttribute(gemm_kernel, cudaFuncAttributeMaxDynamicSharedMemorySize, GEMM_SMEM);

    alpha_topk_kernel<<<1, 256>>>(alpha);
    xhalf_kernel<<<(MROWS * NFEAT) / (256 * 4), 256>>>(x);
    build_w_kernel<<<dim3(NFEAT / TC, NFEAT / TI), 256>>>(V);
    gemm_kernel<<<dim3(NFEAT / BN, MROWS / BM), 256, GEMM_SMEM>>>(out);
}

// round 4
// speedup vs baseline: 1.4581x; 1.1710x over previous
#include <cuda_runtime.h>
#include <cuda_fp16.h>
#include <cstdint>

// ============================================================================
// Problem constants
// ============================================================================
#define NFEAT 4096
#define MROWS 1024
#define KTOP  41.0f
#define WSCALE 4096.0f          // 2^12, exact power of two
#define INV_WSCALE (1.0f/4096.0f)

// Scratch (device globals — allocation-free rule)
__device__ float g_alpha_topk[NFEAT];
__device__ __align__(128) __half g_Wh[(size_t)NFEAT * NFEAT];   // W * 2^12, fp16
__device__ __align__(128) __half g_Xh[(size_t)MROWS * NFEAT];   // x, fp16

// ============================================================================
// Small PTX helpers (base-arch safe: sm_80+ features only)
// ============================================================================
__device__ __forceinline__ uint32_t smem_to_u32(const void* p) {
    uint32_t a;
    asm("{ .reg .u64 t; cvta.to.shared.u64 t, %1; cvt.u32.u64 %0, t; }" : "=r"(a) : "l"(p));
    return a;
}
__device__ __forceinline__ void cp16(uint32_t dst_smem, const void* src) {
    asm volatile("cp.async.cg.shared.global [%0], [%1], 16;" :: "r"(dst_smem), "l"(src) : "memory");
}
#define CP_COMMIT() asm volatile("cp.async.commit_group;" ::: "memory")
#define CP_WAIT1()  asm volatile("cp.async.wait_group 1;"  ::: "memory")

__device__ __forceinline__ void mma16816(float* c, const uint32_t* a, const uint32_t* b) {
    asm volatile(
        "mma.sync.aligned.m16n8k16.row.col.f32.f16.f16.f32 "
        "{%0,%1,%2,%3}, {%4,%5,%6,%7}, {%8,%9}, {%0,%1,%2,%3};"
        : "+f"(c[0]), "+f"(c[1]), "+f"(c[2]), "+f"(c[3])
        : "r"(a[0]), "r"(a[1]), "r"(a[2]), "r"(a[3]), "r"(b[0]), "r"(b[1]));
}
__device__ __forceinline__ void ldmx4(uint32_t* r, uint32_t addr) {
    asm volatile("ldmatrix.sync.aligned.m8n8.x4.shared.b16 {%0,%1,%2,%3}, [%4];"
                 : "=r"(r[0]), "=r"(r[1]), "=r"(r[2]), "=r"(r[3]) : "r"(addr));
}

// ============================================================================
// Kernel 1: soft-top-k (Dykstra collapsed to scalar-shift recurrence).
// ============================================================================
__global__ void alpha_topk_kernel(const float* __restrict__ alpha) {
    const int tid  = threadIdx.x;        // 256 threads, 16 elems each
    const int wid  = tid >> 5;
    const int lane = tid & 31;
    float y0[16];
#pragma unroll
    for (int j = 0; j < 16; j++) y0[j] = alpha[tid + j * 256] * 100.0f;  // /0.01

    __shared__ float wsum[2][8];
    float S = 0.f, p = 0.f;

    for (int it = 0; it < 50; it++) {
        float local = 0.f;
#pragma unroll
        for (int j = 0; j < 16; j++) local += __saturatef(y0[j] + S);
#pragma unroll
        for (int o = 16; o > 0; o >>= 1) local += __shfl_xor_sync(0xffffffffu, local, o);
        if (lane == 0) wsum[it & 1][wid] = local;
        __syncthreads();
        float s8 = 0.f;
#pragma unroll
        for (int w = 0; w < 8; w++) s8 += wsum[it & 1][w];
        float lam = (s8 + (float)NFEAT * p - KTOP) / (float)NFEAT;
        float dS = p - lam;
        S += dS;
        p = lam;
        if (fabsf(dS) < 1e-10f) break;   // uniform across all threads
    }
#pragma unroll
    for (int j = 0; j < 16; j++)
        g_alpha_topk[tid + j * 256] = __saturatef(y0[j] + S);
}

// ============================================================================
// Kernel 2: x -> fp16 (one-time; x is reused 32x in the GEMM)
// ============================================================================
__global__ void xhalf_kernel(const float* __restrict__ X) {
    int i = (blockIdx.x * 256 + threadIdx.x) * 4;   // 4 floats per thread
    float4 v = *reinterpret_cast<const float4*>(X + i);
    __half2 h0 = __floats2half2_rn(v.x, v.y);
    __half2 h1 = __floats2half2_rn(v.z, v.w);
    uint2 packed;
    packed.x = *reinterpret_cast<uint32_t*>(&h0);
    packed.y = *reinterpret_cast<uint32_t*>(&h1);
    *reinterpret_cast<uint2*>(&g_Xh[i]) = packed;
}

// ============================================================================
// Kernel 3: materialize Wh[r,c] = 2^12 * a[i]*V[i,c], r=(i+c)%n — smem diagonal
// transpose: coalesced V reads AND coalesced Wh writes (fp16).
// ============================================================================
#define TI 64
#define TC 128
#define TSTR 132   // mult of 4 (aligned float4 STS); diag read conflict-free

__global__ __launch_bounds__(256) void build_w_kernel(const float* __restrict__ V) {
    __shared__ float tile[TI * TSTR];
    const int tid = threadIdx.x;
    const int i0 = blockIdx.y * TI;
    const int c0 = blockIdx.x * TC;

#pragma unroll
    for (int pp = 0; pp < 8; pp++) {
        int idx = tid + pp * 256;        // 0..2047
        int il  = idx >> 5;              // 0..63
        int jq  = idx & 31;              // float4 index 0..31
        float a = g_alpha_topk[i0 + il] * WSCALE;
        float4 v = *reinterpret_cast<const float4*>(V + (size_t)(i0 + il) * NFEAT + c0 + jq * 4);
        float4 w;
        w.x = a * v.x; w.y = a * v.y; w.z = a * v.z; w.w = a * v.w;
        *reinterpret_cast<float4*>(&tile[il * TSTR + jq * 4]) = w;
    }
    __syncthreads();

    const int sub = tid >> 6;   // 0..3
    const int l64 = tid & 63;
    for (int base = 0; base < TI + TC - 1; base += 4) {
        int d = base + sub;
        if (d < TI + TC - 1) {
            int ccLo = max(0, d - (TI - 1));
            int ccHi = min(TC - 1, d);
            int cc = ccLo + l64;
            if (cc <= ccHi) {
                int il = d - cc;
                int r = (i0 + c0 + d) & (NFEAT - 1);
                g_Wh[(size_t)r * NFEAT + c0 + cc] = __float2half_rn(tile[il * TSTR + cc]);
            }
        }
    }
}

// ============================================================================
// Kernel 4: fp16 GEMM  out[1024,4096] = (Xh @ Wh^T) * 2^-12, fp32 accumulate.
//   128 threads (4 warps, 2x2 grid), warp tile 64x64, BM=BN=128, BK=64 halves,
//   3-stage cp.async pipeline, XOR-swizzled smem, ldmatrix.x4 fragment loads,
//   2 CTAs/SM. Per warp per stage: 128 HMMA, 32 ldmatrix — issue-lean.
// ============================================================================
#define BM 128
#define BN 128
#define NS (NFEAT / 64)          // 64 K-stages
#define STAGE_A 16384            // 128 rows x 128 B
#define STAGE_BYTES 32768
#define GEMM_SMEM (3 * STAGE_BYTES)      // 98304 B

__device__ __forceinline__ void issue_stage(int s, uint32_t sb, int m0, int n0, int tid) {
    if (s < NS) {
        const int buf = s % 3;
        const int k0h = s * 64;
#pragma unroll
        for (int p = 0; p < 8; p++) {
            int idx = tid + p * 128;     // 0..1023
            int row = idx >> 3, j = idx & 7;
            uint32_t off = (uint32_t)(row * 128 + j * 16);
            uint32_t sw  = off ^ (uint32_t)((row & 7) << 4);
            cp16(sb + buf * STAGE_BYTES + sw,
                 g_Xh + (size_t)(m0 + row) * NFEAT + k0h + j * 8);
        }
#pragma unroll
        for (int p = 0; p < 8; p++) {
            int idx = tid + p * 128;
            int row = idx >> 3, j = idx & 7;
            uint32_t off = (uint32_t)(row * 128 + j * 16);
            uint32_t sw  = off ^ (uint32_t)((row & 7) << 4);
            cp16(sb + buf * STAGE_BYTES + STAGE_A + sw,
                 g_Wh + (size_t)(n0 + row) * NFEAT + k0h + j * 8);
        }
    }
    CP_COMMIT();   // empty group past the end keeps wait counts right
}

__global__ __launch_bounds__(128, 2)
void gemm_kernel(float* __restrict__ OUT) {
    extern __shared__ char smem[];
    const uint32_t sb = smem_to_u32(smem);
    const int tid  = threadIdx.x;
    const int wid  = tid >> 5;
    const int lane = tid & 31;
    const int wm   = wid >> 1;           // 0..1 -> 64-row slab
    const int wn   = wid & 1;            // 0..1 -> 64-col slab
    const int m0 = blockIdx.y * BM;
    const int n0 = blockIdx.x * BN;

    float acc[32][4];
#pragma unroll
    for (int i = 0; i < 32; i++)
        acc[i][0] = acc[i][1] = acc[i][2] = acc[i][3] = 0.f;

    // ldmatrix per-lane addressing. lane = mat*8 + rowin.
    const int rowin = lane & 7;
    const int mat   = lane >> 3;
    // A: mat0 (r, k0), mat1 (r+8, k0), mat2 (r, k+8), mat3 (r+8, k+8)
    const int rA = rowin + (mat & 1) * 8;
    const int cA = (mat >> 1) * 16;
    // B: mat0 (n, k0), mat1 (n, k+8), mat2 (n+8, k0), mat3 (n+8, k+8)
    const int rB = rowin + (mat >> 1) * 8;
    const int cB = (mat & 1) * 16;

    uint32_t arow[4], brow[4], koffA[4], koffB[4];
#pragma unroll
    for (int mi = 0; mi < 4; mi++)
        arow[mi] = (uint32_t)((wm * 64 + mi * 16 + rA) * 128);
#pragma unroll
    for (int pr = 0; pr < 4; pr++)
        brow[pr] = (uint32_t)((wn * 64 + pr * 16 + rB) * 128) + STAGE_A;
#pragma unroll
    for (int ks = 0; ks < 4; ks++) {
        koffA[ks] = (uint32_t)((ks * 32 + cA) ^ (rowin << 4));
        koffB[ks] = (uint32_t)((ks * 32 + cB) ^ (rowin << 4));
    }

    issue_stage(0, sb, m0, n0, tid);
    issue_stage(1, sb, m0, n0, tid);

    for (int s = 0; s < NS; s++) {
        CP_WAIT1();
        __syncthreads();
        const uint32_t stg = sb + (uint32_t)((s % 3) * STAGE_BYTES);

#pragma unroll
        for (int ks = 0; ks < 4; ks++) {
            uint32_t af[4][4], bf[8][2];
#pragma unroll
            for (int mi = 0; mi < 4; mi++)
                ldmx4(af[mi], stg + arow[mi] + koffA[ks]);
#pragma unroll
            for (int pr = 0; pr < 4; pr++) {
                uint32_t r[4];
                ldmx4(r, stg + brow[pr] + koffB[ks]);
                bf[pr * 2][0]     = r[0];
                bf[pr * 2][1]     = r[1];
                bf[pr * 2 + 1][0] = r[2];
                bf[pr * 2 + 1][1] = r[3];
            }
#pragma unroll
            for (int mi = 0; mi < 4; mi++)
#pragma unroll
                for (int ni = 0; ni < 8; ni++)
                    mma16816(acc[mi * 8 + ni], af[mi], bf[ni]);
        }

        issue_stage(s + 2, sb, m0, n0, tid);
    }

    // Epilogue: undo 2^12 W scaling; c0,c1 -> (r, c..c+1); c2,c3 -> r+8.
    const int t4 = lane >> 2, tq = lane & 3;
#pragma unroll
    for (int mi = 0; mi < 4; mi++) {
        int r = m0 + wm * 64 + mi * 16 + t4;
#pragma unroll
        for (int ni = 0; ni < 8; ni++) {
            int c = n0 + wn * 64 + ni * 8 + tq * 2;
            float* a = acc[mi * 8 + ni];
            float2 v0 = make_float2(a[0] * INV_WSCALE, a[1] * INV_WSCALE);
            float2 v1 = make_float2(a[2] * INV_WSCALE, a[3] * INV_WSCALE);
            *reinterpret_cast<float2*>(OUT + (size_t)r * NFEAT + c) = v0;
            *reinterpret_cast<float2*>(OUT + (size_t)(r + 8) * NFEAT + c) = v1;
        }
    }
}

// ============================================================================
// Launch
// ============================================================================
extern "C" void kernel_launch(void* const* d_in, const int* in_sizes, int n_in,
                              void* d_out, int out_size) {
    const float* x = nullptr;
    const float* V = nullptr;
    const float* alpha = nullptr;
    for (int i = 0; i < n_in; i++) {
        if (in_sizes[i] == NFEAT)               alpha = (const float*)d_in[i];
        else if (in_sizes[i] == MROWS * NFEAT)  x     = (const float*)d_in[i];
        else                                    V     = (const float*)d_in[i];
    }
    float* out = (float*)d_out;

    cudaFuncSetAttribute(gemm_kernel, cudaFuncAttributeMaxDynamicSharedMemorySize, GEMM_SMEM);

    alpha_topk_kernel<<<1, 256>>>(alpha);
    xhalf_kernel<<<(MROWS * NFEAT) / (256 * 4), 256>>>(x);
    build_w_kernel<<<dim3(NFEAT / TC, NFEAT / TI), 256>>>(V);
    gemm_kernel<<<dim3(NFEAT / BN, MROWS / BM), 128, GEMM_SMEM>>>(out);
}

// round 5
// speedup vs baseline: 1.5232x; 1.0447x over previous
#include <cuda_runtime.h>
#include <cuda_fp16.h>
#include <cstdint>

// ============================================================================
// Problem constants
// ============================================================================
#define NFEAT 4096
#define MROWS 1024
#define KTOP  41.0f
#define WSCALE 4096.0f          // 2^12, exact power of two
#define INV_WSCALE (1.0f/4096.0f)

// Scratch (device globals — allocation-free rule)
__device__ float g_alpha_topk[NFEAT];
__device__ __align__(128) __half g_Wh[(size_t)NFEAT * NFEAT];   // W * 2^12, fp16
__device__ __align__(128) __half g_Xh[(size_t)MROWS * NFEAT];   // x, fp16

// ============================================================================
// Small PTX helpers (base-arch safe: sm_80+ features only)
// ============================================================================
__device__ __forceinline__ uint32_t smem_to_u32(const void* p) {
    uint32_t a;
    asm("{ .reg .u64 t; cvta.to.shared.u64 t, %1; cvt.u32.u64 %0, t; }" : "=r"(a) : "l"(p));
    return a;
}
__device__ __forceinline__ void cp16(uint32_t dst_smem, const void* src) {
    asm volatile("cp.async.cg.shared.global [%0], [%1], 16;" :: "r"(dst_smem), "l"(src) : "memory");
}
#define CP_COMMIT() asm volatile("cp.async.commit_group;" ::: "memory")
#define CP_WAIT1()  asm volatile("cp.async.wait_group 1;"  ::: "memory")

__device__ __forceinline__ void mma16816(float* c, const uint32_t* a, const uint32_t* b) {
    asm volatile(
        "mma.sync.aligned.m16n8k16.row.col.f32.f16.f16.f32 "
        "{%0,%1,%2,%3}, {%4,%5,%6,%7}, {%8,%9}, {%0,%1,%2,%3};"
        : "+f"(c[0]), "+f"(c[1]), "+f"(c[2]), "+f"(c[3])
        : "r"(a[0]), "r"(a[1]), "r"(a[2]), "r"(a[3]), "r"(b[0]), "r"(b[1]));
}
__device__ __forceinline__ void ldmx4(uint32_t* r, uint32_t addr) {
    asm volatile("ldmatrix.sync.aligned.m8n8.x4.shared.b16 {%0,%1,%2,%3}, [%4];"
                 : "=r"(r[0]), "=r"(r[1]), "=r"(r[2]), "=r"(r[3]) : "r"(addr));
}

// ============================================================================
// Kernel 1 (merged): blocks 0..1023 convert x -> fp16; block 1024 runs the
// soft-top-k. Dykstra collapses further: substituting lambda into the update,
// p cancels exactly:  S' = S + (k - sum(clip(y0+S,0,1)))/n.
// Contraction 1-m/n ~ 0.094 => |dS| < 1e-9 by iter ~10 => break fires.
// ============================================================================
__global__ void prep_kernel(const float* __restrict__ alpha, const float* __restrict__ X) {
    if (blockIdx.x < 1024) {
        // x -> fp16, 16 floats/thread, coalesced float4 accesses
        const int blk = blockIdx.x * 4096;
        const int t4  = threadIdx.x * 4;
#pragma unroll
        for (int q = 0; q < 4; q++) {
            int i = blk + q * 1024 + t4;
            float4 v = *reinterpret_cast<const float4*>(X + i);
            __half2 h0 = __floats2half2_rn(v.x, v.y);
            __half2 h1 = __floats2half2_rn(v.z, v.w);
            uint2 packed;
            packed.x = *reinterpret_cast<uint32_t*>(&h0);
            packed.y = *reinterpret_cast<uint32_t*>(&h1);
            *reinterpret_cast<uint2*>(&g_Xh[i]) = packed;
        }
        return;
    }

    // soft-top-k block (256 threads, 16 elems each)
    const int tid  = threadIdx.x;
    const int wid  = tid >> 5;
    const int lane = tid & 31;
    float y0[16];
#pragma unroll
    for (int j = 0; j < 16; j++) y0[j] = alpha[tid + j * 256] * 100.0f;  // /0.01

    __shared__ float wsum[2][8];
    float S = 0.f;

    for (int it = 0; it < 50; it++) {
        float local = 0.f;
#pragma unroll
        for (int j = 0; j < 16; j++) local += __saturatef(y0[j] + S);
#pragma unroll
        for (int o = 16; o > 0; o >>= 1) local += __shfl_xor_sync(0xffffffffu, local, o);
        if (lane == 0) wsum[it & 1][wid] = local;
        __syncthreads();
        float f = 0.f;
#pragma unroll
        for (int w = 0; w < 8; w++) f += wsum[it & 1][w];
        float dS = (KTOP - f) / (float)NFEAT;
        S += dS;
        if (fabsf(dS) < 1e-9f) break;    // uniform branch; fires ~iter 10
    }
#pragma unroll
    for (int j = 0; j < 16; j++)
        g_alpha_topk[tid + j * 256] = __saturatef(y0[j] + S);
}

// ============================================================================
// Kernel 2: materialize Wh[r,c] = 2^12 * a[i]*V[i,c], r=(i+c)%n — smem diagonal
// transpose: coalesced V reads AND coalesced Wh writes (fp16).
// ============================================================================
#define TI 64
#define TC 128
#define TSTR 132   // mult of 4 (aligned float4 STS); diag read conflict-free

__global__ __launch_bounds__(256) void build_w_kernel(const float* __restrict__ V) {
    __shared__ float tile[TI * TSTR];
    const int tid = threadIdx.x;
    const int i0 = blockIdx.y * TI;
    const int c0 = blockIdx.x * TC;

#pragma unroll
    for (int pp = 0; pp < 8; pp++) {
        int idx = tid + pp * 256;        // 0..2047
        int il  = idx >> 5;              // 0..63
        int jq  = idx & 31;              // float4 index 0..31
        float a = g_alpha_topk[i0 + il] * WSCALE;
        float4 v = *reinterpret_cast<const float4*>(V + (size_t)(i0 + il) * NFEAT + c0 + jq * 4);
        float4 w;
        w.x = a * v.x; w.y = a * v.y; w.z = a * v.z; w.w = a * v.w;
        *reinterpret_cast<float4*>(&tile[il * TSTR + jq * 4]) = w;
    }
    __syncthreads();

    const int sub = tid >> 6;   // 0..3
    const int l64 = tid & 63;
    for (int base = 0; base < TI + TC - 1; base += 4) {
        int d = base + sub;
        if (d < TI + TC - 1) {
            int ccLo = max(0, d - (TI - 1));
            int ccHi = min(TC - 1, d);
            int cc = ccLo + l64;
            if (cc <= ccHi) {
                int il = d - cc;
                int r = (i0 + c0 + d) & (NFEAT - 1);
                g_Wh[(size_t)r * NFEAT + c0 + cc] = __float2half_rn(tile[il * TSTR + cc]);
            }
        }
    }
}

// ============================================================================
// Kernel 3: fp16 GEMM  out[1024,4096] = (Xh @ Wh^T) * 2^-12, fp32 accumulate.
//   128 threads (4 warps, 2x2), warp tile 64x64, BM=BN=128, BK=64 halves,
//   3-stage cp.async pipeline (issue hoisted ABOVE the mma block for max
//   latency headroom), XOR-swizzled smem, ldmatrix.x4, 2 CTAs/SM.
// ============================================================================
#define BM 128
#define BN 128
#define NS (NFEAT / 64)          // 64 K-stages
#define STAGE_A 16384            // 128 rows x 128 B
#define STAGE_BYTES 32768
#define GEMM_SMEM (3 * STAGE_BYTES)      // 98304 B

__device__ __forceinline__ void issue_stage(int s, uint32_t sb, int m0, int n0, int tid) {
    if (s < NS) {
        const int buf = s % 3;
        const int k0h = s * 64;
#pragma unroll
        for (int p = 0; p < 8; p++) {
            int idx = tid + p * 128;     // 0..1023
            int row = idx >> 3, j = idx & 7;
            uint32_t off = (uint32_t)(row * 128 + j * 16);
            uint32_t sw  = off ^ (uint32_t)((row & 7) << 4);
            cp16(sb + buf * STAGE_BYTES + sw,
                 g_Xh + (size_t)(m0 + row) * NFEAT + k0h + j * 8);
        }
#pragma unroll
        for (int p = 0; p < 8; p++) {
            int idx = tid + p * 128;
            int row = idx >> 3, j = idx & 7;
            uint32_t off = (uint32_t)(row * 128 + j * 16);
            uint32_t sw  = off ^ (uint32_t)((row & 7) << 4);
            cp16(sb + buf * STAGE_BYTES + STAGE_A + sw,
                 g_Wh + (size_t)(n0 + row) * NFEAT + k0h + j * 8);
        }
    }
    CP_COMMIT();   // empty group past the end keeps wait counts right
}

__global__ __launch_bounds__(128, 2)
void gemm_kernel(float* __restrict__ OUT) {
    extern __shared__ char smem[];
    const uint32_t sb = smem_to_u32(smem);
    const int tid  = threadIdx.x;
    const int wid  = tid >> 5;
    const int lane = tid & 31;
    const int wm   = wid >> 1;           // 0..1 -> 64-row slab
    const int wn   = wid & 1;            // 0..1 -> 64-col slab
    const int m0 = blockIdx.y * BM;
    const int n0 = blockIdx.x * BN;

    float acc[32][4];
#pragma unroll
    for (int i = 0; i < 32; i++)
        acc[i][0] = acc[i][1] = acc[i][2] = acc[i][3] = 0.f;

    // ldmatrix per-lane addressing. lane = mat*8 + rowin.
    const int rowin = lane & 7;
    const int mat   = lane >> 3;
    const int rA = rowin + (mat & 1) * 8;
    const int cA = (mat >> 1) * 16;
    const int rB = rowin + (mat >> 1) * 8;
    const int cB = (mat & 1) * 16;

    uint32_t arow[4], brow[4], koffA[4], koffB[4];
#pragma unroll
    for (int mi = 0; mi < 4; mi++)
        arow[mi] = (uint32_t)((wm * 64 + mi * 16 + rA) * 128);
#pragma unroll
    for (int pr = 0; pr < 4; pr++)
        brow[pr] = (uint32_t)((wn * 64 + pr * 16 + rB) * 128) + STAGE_A;
#pragma unroll
    for (int ks = 0; ks < 4; ks++) {
        koffA[ks] = (uint32_t)((ks * 32 + cA) ^ (rowin << 4));
        koffB[ks] = (uint32_t)((ks * 32 + cB) ^ (rowin << 4));
    }

    issue_stage(0, sb, m0, n0, tid);
    issue_stage(1, sb, m0, n0, tid);

    for (int s = 0; s < NS; s++) {
        CP_WAIT1();
        __syncthreads();
        // Hoisted: all warps passed the barrier => mma(s-1) is complete, so
        // overwriting buffer (s+2)%3 == (s-1)%3 is safe; the LDGSTS issue now
        // overlaps this stage's HMMA and gains a full stage of L2 headroom.
        issue_stage(s + 2, sb, m0, n0, tid);

        const uint32_t stg = sb + (uint32_t)((s % 3) * STAGE_BYTES);
#pragma unroll
        for (int ks = 0; ks < 4; ks++) {
            uint32_t af[4][4], bf[8][2];
#pragma unroll
            for (int mi = 0; mi < 4; mi++)
                ldmx4(af[mi], stg + arow[mi] + koffA[ks]);
#pragma unroll
            for (int pr = 0; pr < 4; pr++) {
                uint32_t r[4];
                ldmx4(r, stg + brow[pr] + koffB[ks]);
                bf[pr * 2][0]     = r[0];
                bf[pr * 2][1]     = r[1];
                bf[pr * 2 + 1][0] = r[2];
                bf[pr * 2 + 1][1] = r[3];
            }
#pragma unroll
            for (int mi = 0; mi < 4; mi++)
#pragma unroll
                for (int ni = 0; ni < 8; ni++)
                    mma16816(acc[mi * 8 + ni], af[mi], bf[ni]);
        }
    }

    // Epilogue: undo 2^12 W scaling; c0,c1 -> (r, c..c+1); c2,c3 -> r+8.
    const int t4 = lane >> 2, tq = lane & 3;
#pragma unroll
    for (int mi = 0; mi < 4; mi++) {
        int r = m0 + wm * 64 + mi * 16 + t4;
#pragma unroll
        for (int ni = 0; ni < 8; ni++) {
            int c = n0 + wn * 64 + ni * 8 + tq * 2;
            float* a = acc[mi * 8 + ni];
            float2 v0 = make_float2(a[0] * INV_WSCALE, a[1] * INV_WSCALE);
            float2 v1 = make_float2(a[2] * INV_WSCALE, a[3] * INV_WSCALE);
            *reinterpret_cast<float2*>(OUT + (size_t)r * NFEAT + c) = v0;
            *reinterpret_cast<float2*>(OUT + (size_t)(r + 8) * NFEAT + c) = v1;
        }
    }
}

// ============================================================================
// Launch
// ============================================================================
extern "C" void kernel_launch(void* const* d_in, const int* in_sizes, int n_in,
                              void* d_out, int out_size) {
    const float* x = nullptr;
    const float* V = nullptr;
    const float* alpha = nullptr;
    for (int i = 0; i < n_in; i++) {
        if (in_sizes[i] == NFEAT)               alpha = (const float*)d_in[i];
        else if (in_sizes[i] == MROWS * NFEAT)  x     = (const float*)d_in[i];
        else                                    V     = (const float*)d_in[i];
    }
    float* out = (float*)d_out;

    cudaFuncSetAttribute(gemm_kernel, cudaFuncAttributeMaxDynamicSharedMemorySize, GEMM_SMEM);

    prep_kernel<<<1025, 256>>>(alpha, x);
    build_w_kernel<<<dim3(NFEAT / TC, NFEAT / TI), 256>>>(V);
    gemm_kernel<<<dim3(NFEAT / BN, MROWS / BM), 128, GEMM_SMEM>>>(out);
}